// round 5
// baseline (speedup 1.0000x reference)
#include <cuda_runtime.h>
#include <cuda_bf16.h>
#include <cstdint>

// Problem constants
#define BB   16
#define DD   128
#define TT   4096
#define NN   (BB * TT)        // 65536 rows
#define NC   1024             // codebook size
#define QELEMS (BB * DD * TT) // 8388608
#define MARGIN 1.0e-3f        // >> worst-case 3-group split d2 error

#define KDIM 384              // [hi | hi | lo] x  vs  [hi | lo | hi] e
#define KPAD 392              // smem row pad: word stride 196 ≡ 4 (mod 32) -> conflict-free frags
#define KW   (KPAD / 2)       // 196 u32 words per padded row
#define ROWB (KDIM * 2)       // 768 bytes per row in gmem

// ---------------- device scratch (globals; no allocation allowed) ----------------
__device__ __nv_bfloat16 g_xsplit[(size_t)NN * KDIM]; // [row][hi128|hi128|lo128]
__device__ __nv_bfloat16 g_esplit[(size_t)NC * KDIM]; // [code][hi128|lo128|hi128]
__device__ float g_rq[NN];
__device__ float g_enorm[NC];
__device__ float g_rowd2[NN];
__device__ int   g_indices[NN];
__device__ float g_used[NC];
__device__ int   g_hard[NN];
__device__ int   g_hardcnt;
__device__ float g_partial[128];

// ---------------- helpers ----------------
__device__ __forceinline__ uint32_t smem_u32(const void* p) {
    uint32_t a;
    asm("{ .reg .u64 t; cvta.to.shared.u64 t, %1; cvt.u32.u64 %0, t; }" : "=r"(a) : "l"(p));
    return a;
}
__device__ __forceinline__ void cp_async16(uint32_t dst, const void* src) {
    asm volatile("cp.async.ca.shared.global [%0], [%1], 16;" :: "r"(dst), "l"(src) : "memory");
}
__device__ __forceinline__ void cp_commit() { asm volatile("cp.async.commit_group;" ::: "memory"); }
__device__ __forceinline__ void cp_wait1()  { asm volatile("cp.async.wait_group 1;" ::: "memory"); }
__device__ __forceinline__ void cp_wait0()  { asm volatile("cp.async.wait_group 0;" ::: "memory"); }

__device__ __forceinline__ void hmma16816(float* c, uint32_t a0, uint32_t a1, uint32_t a2,
                                          uint32_t a3, uint32_t b0, uint32_t b1) {
    asm volatile(
        "mma.sync.aligned.m16n8k16.row.col.f32.bf16.bf16.f32 "
        "{%0,%1,%2,%3}, {%4,%5,%6,%7}, {%8,%9}, {%0,%1,%2,%3};"
        : "+f"(c[0]), "+f"(c[1]), "+f"(c[2]), "+f"(c[3])
        : "r"(a0), "r"(a1), "r"(a2), "r"(a3), "r"(b0), "r"(b1));
}

__device__ __forceinline__ uint32_t pack_bf16(float a, float b) {
    __nv_bfloat16 ah = __float2bfloat16_rn(a), bh = __float2bfloat16_rn(b);
    return (uint32_t)__bfloat16_as_ushort(ah) | ((uint32_t)__bfloat16_as_ushort(bh) << 16);
}
__device__ __forceinline__ uint32_t pack_bf16_lo(float a, float b) {
    __nv_bfloat16 ah = __float2bfloat16_rn(a), bh = __float2bfloat16_rn(b);
    float al = a - __bfloat162float(ah), bl = b - __bfloat162float(bh);
    return (uint32_t)__bfloat16_as_ushort(__float2bfloat16_rn(al)) |
           ((uint32_t)__bfloat16_as_ushort(__float2bfloat16_rn(bl)) << 16);
}

// ---------------- kernel 0: e norms, e split [hi|lo|hi], zero flags ----------------
__global__ void vq_init(const float* __restrict__ embed) {
    int c = blockIdx.x * 256 + threadIdx.x;
    if (c == 0) g_hardcnt = 0;
    if (c < NC) {
        const float* e = embed + (size_t)c * DD;
        float s = 0.f;
        #pragma unroll 8
        for (int k = 0; k < DD; ++k) s = __fmaf_rn(e[k], e[k], s);
        g_enorm[c] = s;
        g_used[c] = 0.f;
        uint32_t* dst = reinterpret_cast<uint32_t*>(g_esplit + (size_t)c * KDIM);
        #pragma unroll 4
        for (int w = 0; w < 64; ++w) {
            float a = e[2 * w], b = e[2 * w + 1];
            dst[w]       = pack_bf16(a, b);      // hi, k 0..127
            dst[64 + w]  = pack_bf16_lo(a, b);   // lo, k 128..255
            dst[128 + w] = pack_bf16(a, b);      // hi, k 256..383
        }
    }
}

// ---------------- kernel 1: x transpose + split [hi|hi|lo] + row norms ----------------
#define CS 129
__global__ void __launch_bounds__(256) vq_convert(const float* __restrict__ x) {
    extern __shared__ float xs[];   // [128 t][CS]
    const int tid = threadIdx.x;
    const int t0 = blockIdx.x * 128;
    const int bb = blockIdx.y;
    const float* xb = x + (size_t)bb * DD * TT;

    #pragma unroll
    for (int it = 0; it < 16; ++it) {
        int f = tid + it * 256;       // 0..4095
        int d = f >> 5;               // 0..127
        int v = f & 31;               // float4 along t
        float4 val = *reinterpret_cast<const float4*>(xb + (size_t)d * TT + t0 + v * 4);
        xs[(v * 4 + 0) * CS + d] = val.x;
        xs[(v * 4 + 1) * CS + d] = val.y;
        xs[(v * 4 + 2) * CS + d] = val.z;
        xs[(v * 4 + 3) * CS + d] = val.w;
    }
    __syncthreads();

    if (tid < 128) {
        float s = 0.f;
        #pragma unroll 8
        for (int k = 0; k < DD; ++k) { float v = xs[tid * CS + k]; s = __fmaf_rn(v, v, s); }
        g_rq[(size_t)bb * TT + t0 + tid] = s;
    }

    // 2 threads per row; each writes 96 u32 of its row's 192-word split
    {
        const int row  = tid >> 1;
        const int half = tid & 1;
        const float* xr = xs + row * CS;
        uint32_t* out = reinterpret_cast<uint32_t*>(g_xsplit) +
                        ((size_t)bb * TT + t0 + row) * (KDIM / 2) + half * 96;
        #pragma unroll 4
        for (int i = 0; i < 96; ++i) {
            int w = half * 96 + i;    // 0..191
            uint32_t v;
            if (w < 64)        v = pack_bf16(xr[2 * w], xr[2 * w + 1]);             // hi
            else if (w < 128)  v = pack_bf16(xr[2 * (w - 64)], xr[2 * (w - 64) + 1]); // hi dup
            else               v = pack_bf16_lo(xr[2 * (w - 128)], xr[2 * (w - 128) + 1]); // lo
            out[i] = v;
        }
    }
}

// ---------------- kernel 2: HMMA GEMM + best/second argmin ----------------
// CTA: 128 rows, 16 chunks of 64 codes, K=384. 8 warps; warp w owns rows
// [w*16, w*16+16) x all 64 chunk codes. Fragments loaded as LDS.32 from
// K-padded smem (word stride 196 -> banks (4g+t4)%32, conflict-free).
#define ASM_BYTES (128 * KPAD * 2)            // 100352
#define BBUF_BYTES (64 * KPAD * 2)            // 50176
#define SMEM_MMA (ASM_BYTES + 2 * BBUF_BYTES) // 200704

__global__ void __launch_bounds__(256) vq_mma(void) {
    extern __shared__ char smem[];
    uint32_t* As = reinterpret_cast<uint32_t*>(smem);                 // [128][KW]
    uint32_t* Bs = As + 128 * KW;                                     // 2 x [64][KW]
    const uint32_t As_a = smem_u32(smem);
    const uint32_t Bs_a = As_a + ASM_BYTES;

    const int tid = threadIdx.x;
    const int wid = tid >> 5, lane = tid & 31;
    const int g = lane >> 2, t4 = lane & 3;
    const int m0 = wid * 16;
    const int row0 = blockIdx.x * 128;

    const char* xsrc = reinterpret_cast<const char*>(g_xsplit) + (size_t)row0 * ROWB;
    const char* esrc = reinterpret_cast<const char*>(g_esplit);

    // Prologue: A + B0 in group0, B1 in group1
    #pragma unroll
    for (int i = 0; i < 24; ++i) {             // A: 128 rows x 48 x16B
        int f = tid + i * 256;                 // 0..6143
        int r = f / 48, v = f % 48;
        cp_async16(As_a + r * (KPAD * 2) + v * 16, xsrc + (size_t)r * ROWB + v * 16);
    }
    #pragma unroll
    for (int i = 0; i < 12; ++i) {             // B0: 64 codes x 48 x16B
        int f = tid + i * 256;                 // 0..3071
        int cc = f / 48, v = f % 48;
        cp_async16(Bs_a + cc * (KPAD * 2) + v * 16, esrc + (size_t)cc * ROWB + v * 16);
    }
    cp_commit();
    #pragma unroll
    for (int i = 0; i < 12; ++i) {
        int f = tid + i * 256;
        int cc = f / 48, v = f % 48;
        cp_async16(Bs_a + BBUF_BYTES + cc * (KPAD * 2) + v * 16,
                   esrc + (size_t)(64 + cc) * ROWB + v * 16);
    }
    cp_commit();

    const float rq0 = g_rq[row0 + m0 + g];
    const float rq1 = g_rq[row0 + m0 + g + 8];
    float best0 = 3.4e38f, sec0 = 3.4e38f; int idx0 = 0;
    float best1 = 3.4e38f, sec1 = 3.4e38f; int idx1 = 0;

    const uint32_t* arow0 = As + (m0 + g) * KW;
    const uint32_t* arow1 = As + (m0 + g + 8) * KW;

    for (int ct = 0; ct < 16; ++ct) {
        if (ct < 15) cp_wait1(); else cp_wait0();
        __syncthreads();

        const uint32_t* Bc = Bs + (ct & 1) * (BBUF_BYTES / 4);
        float acc[8][4];
        #pragma unroll
        for (int nt = 0; nt < 8; ++nt)
            #pragma unroll
            for (int r = 0; r < 4; ++r) acc[nt][r] = 0.f;

        #pragma unroll 2
        for (int ks = 0; ks < KDIM / 16; ++ks) {       // 24 k-steps
            const int kp = ks * 8 + t4;                // u32 pair index
            uint32_t a0 = arow0[kp],     a1 = arow1[kp];
            uint32_t a2 = arow0[kp + 4], a3 = arow1[kp + 4];
            #pragma unroll
            for (int nt = 0; nt < 8; ++nt) {
                const uint32_t* brow = Bc + (nt * 8 + g) * KW;
                uint32_t b0 = brow[kp], b1 = brow[kp + 4];
                hmma16816(acc[nt], a0, a1, a2, a3, b0, b1);
            }
        }

        // epilogue: distances + best/second update (cols ascend -> lowest-index ties)
        #pragma unroll
        for (int nt = 0; nt < 8; ++nt) {
            int col = ct * 64 + nt * 8 + t4 * 2;
            float en0 = __ldg(&g_enorm[col]);
            float en1 = __ldg(&g_enorm[col + 1]);
            float s00 = __fadd_rn(__fsub_rn(rq0, __fmul_rn(2.f, acc[nt][0])), en0);
            float s01 = __fadd_rn(__fsub_rn(rq0, __fmul_rn(2.f, acc[nt][1])), en1);
            float s10 = __fadd_rn(__fsub_rn(rq1, __fmul_rn(2.f, acc[nt][2])), en0);
            float s11 = __fadd_rn(__fsub_rn(rq1, __fmul_rn(2.f, acc[nt][3])), en1);
            if (s00 < best0) { sec0 = best0; best0 = s00; idx0 = col; }
            else if (s00 < sec0) sec0 = s00;
            if (s01 < best0) { sec0 = best0; best0 = s01; idx0 = col + 1; }
            else if (s01 < sec0) sec0 = s01;
            if (s10 < best1) { sec1 = best1; best1 = s10; idx1 = col; }
            else if (s10 < sec1) sec1 = s10;
            if (s11 < best1) { sec1 = best1; best1 = s11; idx1 = col + 1; }
            else if (s11 < sec1) sec1 = s11;
        }
        __syncthreads();
        if (ct + 2 < 16) {
            uint32_t dstb = Bs_a + (ct & 1) * BBUF_BYTES;
            const char* src = esrc + (size_t)(ct + 2) * 64 * ROWB;
            #pragma unroll
            for (int i = 0; i < 12; ++i) {
                int f = tid + i * 256;
                int cc = f / 48, v = f % 48;
                cp_async16(dstb + cc * (KPAD * 2) + v * 16, src + (size_t)cc * ROWB + v * 16);
            }
            cp_commit();
        }
    }

    // merge (best, second, idx) across the 4 col-lanes (t4 via xor 1, 2)
    #pragma unroll
    for (int off = 1; off <= 2; off <<= 1) {
        float ob0 = __shfl_xor_sync(0xffffffffu, best0, off);
        float os0 = __shfl_xor_sync(0xffffffffu, sec0, off);
        int   oi0 = __shfl_xor_sync(0xffffffffu, idx0, off);
        float ns0 = fminf(fminf(sec0, os0), fmaxf(best0, ob0));
        if (ob0 < best0 || (ob0 == best0 && oi0 < idx0)) { best0 = ob0; idx0 = oi0; }
        sec0 = ns0;
        float ob1 = __shfl_xor_sync(0xffffffffu, best1, off);
        float os1 = __shfl_xor_sync(0xffffffffu, sec1, off);
        int   oi1 = __shfl_xor_sync(0xffffffffu, idx1, off);
        float ns1 = fminf(fminf(sec1, os1), fmaxf(best1, ob1));
        if (ob1 < best1 || (ob1 == best1 && oi1 < idx1)) { best1 = ob1; idx1 = oi1; }
        sec1 = ns1;
    }

    if (t4 == 0) {
        int r0 = row0 + m0 + g;
        int r1 = r0 + 8;
        g_rowd2[r0] = best0; g_indices[r0] = idx0;
        g_rowd2[r1] = best1; g_indices[r1] = idx1;
        if (sec0 - best0 <= MARGIN) { int h = atomicAdd(&g_hardcnt, 1); g_hard[h] = r0; }
        else g_used[idx0] = 1.f;
        if (sec1 - best1 <= MARGIN) { int h = atomicAdd(&g_hardcnt, 1); g_hard[h] = r1; }
        else g_used[idx1] = 1.f;
    }
}

// ---------------- kernel 3: exact rescore of hard rows (R3 chain, bit-faithful) ----------------
__global__ void __launch_bounds__(256) vq_rescore(const float* __restrict__ x,
                                                  const float* __restrict__ embed) {
    __shared__ float xr[128];
    __shared__ float rqs;
    __shared__ float bv[8];
    __shared__ int   bi[8];
    const int tid = threadIdx.x;
    const int wid = tid >> 5, lane = tid & 31;
    const int cnt = g_hardcnt;

    for (int h = blockIdx.x; h < cnt; h += gridDim.x) {
        const int row = g_hard[h];
        const int bb = row >> 12, t = row & 4095;
        if (tid < 128) xr[tid] = x[((size_t)bb * DD + tid) * TT + t];
        __syncthreads();
        if (tid == 0) {
            float s = 0.f;
            #pragma unroll 8
            for (int k = 0; k < DD; ++k) s = __fmaf_rn(xr[k], xr[k], s);
            rqs = s;
        }
        __syncthreads();
        const float rq = rqs;

        float best = 3.4e38f; int bidx = 0;
        for (int c = tid; c < NC; c += 256) {   // ascending per thread
            const float* e = embed + (size_t)c * DD;
            float ae = 0.f, ao = 0.f;           // even/odd == R3's f32x2 lanes
            #pragma unroll 8
            for (int k = 0; k < DD; k += 2) {
                ae = __fmaf_rn(xr[k],     __ldg(e + k),     ae);
                ao = __fmaf_rn(xr[k + 1], __ldg(e + k + 1), ao);
            }
            float dot = __fadd_rn(ae, ao);
            float s = __fadd_rn(__fsub_rn(rq, __fmul_rn(2.f, dot)), __ldg(&g_enorm[c]));
            if (s < best) { best = s; bidx = c; }
        }
        #pragma unroll
        for (int off = 16; off >= 1; off >>= 1) {
            float ov = __shfl_xor_sync(0xffffffffu, best, off);
            int   oi = __shfl_xor_sync(0xffffffffu, bidx, off);
            if (ov < best || (ov == best && oi < bidx)) { best = ov; bidx = oi; }
        }
        if (lane == 0) { bv[wid] = best; bi[wid] = bidx; }
        __syncthreads();
        if (tid == 0) {
            float B = bv[0]; int I = bi[0];
            #pragma unroll
            for (int w = 1; w < 8; ++w)
                if (bv[w] < B || (bv[w] == B && bi[w] < I)) { B = bv[w]; I = bi[w]; }
            g_indices[row] = I;
            g_rowd2[row] = B;
            g_used[I] = 1.f;
        }
        __syncthreads();
    }
}

// ---------------- kernel 4: gather + transposed write (+ indices as f32) ----------------
#define WPAD 133
__global__ void __launch_bounds__(256) vq_write(const float* __restrict__ embed,
                                                float* __restrict__ out,
                                                int write_idx) {
    extern __shared__ float sm[];
    int*   sidx = (int*)sm;        // [128]
    float* srow = sm + 128;        // [128][WPAD]
    const int tid = threadIdx.x;
    const int t0 = blockIdx.x * 128;
    const int bb = blockIdx.y;
    const int nbase = bb * TT + t0;

    if (tid < 128) {
        int c = g_indices[nbase + tid];
        sidx[tid] = c;
        if (write_idx) out[(size_t)QELEMS + nbase + tid] = (float)c;
    }
    __syncthreads();
    #pragma unroll 4
    for (int it = 0; it < 16; ++it) {
        int f = tid + it * 256;
        int tl = f >> 5;
        int v  = f & 31;
        float4 val = *reinterpret_cast<const float4*>(embed + (size_t)sidx[tl] * DD + v * 4);
        float* dst = srow + tl * WPAD + v * 4;
        dst[0] = val.x; dst[1] = val.y; dst[2] = val.z; dst[3] = val.w;
    }
    __syncthreads();
    float* ob = out + (size_t)bb * DD * TT + t0;
    #pragma unroll 8
    for (int it = 0; it < 64; ++it) {
        int f = tid + it * 256;
        int d = f >> 7;
        int t = f & 127;
        ob[(size_t)d * TT + t] = srow[t * WPAD + d];
    }
}

// ---------------- kernel 5: loss partials (fixed order, deterministic) ----------------
__global__ void __launch_bounds__(256) vq_reduce(void) {
    __shared__ float s1[256];
    const int tid = threadIdx.x;
    const int base = blockIdx.x * 512;
    s1[tid] = __fadd_rn(g_rowd2[base + tid * 2], g_rowd2[base + tid * 2 + 1]);
    __syncthreads();
    for (int off = 128; off > 0; off >>= 1) {
        if (tid < off) s1[tid] += s1[tid + off];
        __syncthreads();
    }
    if (tid == 0) g_partial[blockIdx.x] = s1[0];
}

// ---------------- kernel 6: finalize ----------------
__global__ void vq_finalize(float* __restrict__ out, int out_size) {
    __shared__ float s1[256], s2[256];
    int tid = threadIdx.x;
    float a = 0.f, b = 0.f;
    if (tid < 128) a = g_partial[tid];
    for (int i = tid; i < NC; i += 256) b += g_used[i];
    s1[tid] = a; s2[tid] = b;
    __syncthreads();
    for (int off = 128; off > 0; off >>= 1) {
        if (tid < off) { s1[tid] += s1[tid + off]; s2[tid] += s2[tid + off]; }
        __syncthreads();
    }
    if (tid == 0) {
        long long base = (long long)QELEMS + NN;   // 8454144
        if ((long long)out_size >= base + 2) {
            out[base]     = 2.0f * s1[0] / ((float)NN * (float)DD);  // loss
            out[base + 1] = s2[0] / (float)NC;                       // utilization
        }
    }
}

// ---------------- launch ----------------
extern "C" void kernel_launch(void* const* d_in, const int* in_sizes, int n_in,
                              void* d_out, int out_size) {
    const float* x     = (const float*)d_in[0];
    const float* embed = (const float*)d_in[1];
    float* out = (float*)d_out;

    const int smemC = 128 * CS * (int)sizeof(float);                 // 66048
    const int smemW = (128 + 128 * WPAD) * (int)sizeof(float);       // 68608
    cudaFuncSetAttribute(vq_convert, cudaFuncAttributeMaxDynamicSharedMemorySize, smemC);
    cudaFuncSetAttribute(vq_mma,     cudaFuncAttributeMaxDynamicSharedMemorySize, SMEM_MMA);
    cudaFuncSetAttribute(vq_write,   cudaFuncAttributeMaxDynamicSharedMemorySize, smemW);

    int write_idx = (out_size >= QELEMS + NN) ? 1 : 0;

    vq_init<<<(NC + 255) / 256, 256>>>(embed);
    dim3 gc(TT / 128, BB);
    vq_convert<<<gc, 256, smemC>>>(x);
    vq_mma<<<NN / 128, 256, SMEM_MMA>>>();
    vq_rescore<<<256, 256>>>(x, embed);
    vq_write<<<gc, 256, smemW>>>(embed, out, write_idx);
    vq_reduce<<<NN / 512, 256>>>();
    vq_finalize<<<1, 256>>>(out, out_size);
}

// round 8
// speedup vs baseline: 1.4317x; 1.4317x over previous
#include <cuda_runtime.h>
#include <cuda_bf16.h>
#include <cstdint>

// Problem constants
#define BB   16
#define DD   128
#define TT   4096
#define NN   (BB * TT)        // 65536 rows
#define NC   1024             // codebook size
#define QELEMS (BB * DD * TT) // 8388608
#define MARGIN 1.2e-4f        // ~10x the approx-d2 discrepancy (split err + ref ulp grid)

#define KDIM 384              // [hi | hi | lo] x  vs  [hi | lo | hi] e
#define KPAD 392              // row stride 784 B ≡ 16 (mod 128) -> ldmatrix conflict-free
#define KW   (KPAD / 2)
#define ROWB (KDIM * 2)

// ---------------- device scratch ----------------
__device__ __nv_bfloat16 g_xsplit[(size_t)NN * KDIM];
__device__ __nv_bfloat16 g_esplit[(size_t)NC * KDIM];
__device__ float g_rq[NN];
__device__ float g_enorm[NC];
__device__ float g_rowd2[NN];
__device__ int   g_indices[NN];
__device__ float g_used[NC];
__device__ int   g_hard[NN];
__device__ int   g_hardcnt;
__device__ float g_partial[128];
__device__ float g_cand_val[8 * NN];
__device__ int   g_cand_idx[8 * NN];

// ---------------- helpers ----------------
__device__ __forceinline__ uint32_t smem_u32(const void* p) {
    uint32_t a;
    asm("{ .reg .u64 t; cvta.to.shared.u64 t, %1; cvt.u32.u64 %0, t; }" : "=r"(a) : "l"(p));
    return a;
}
__device__ __forceinline__ void cp_async16(uint32_t dst, const void* src) {
    asm volatile("cp.async.ca.shared.global [%0], [%1], 16;" :: "r"(dst), "l"(src) : "memory");
}
__device__ __forceinline__ void cp_commit() { asm volatile("cp.async.commit_group;" ::: "memory"); }
__device__ __forceinline__ void cp_wait1()  { asm volatile("cp.async.wait_group 1;" ::: "memory"); }
__device__ __forceinline__ void cp_wait0()  { asm volatile("cp.async.wait_group 0;" ::: "memory"); }

__device__ __forceinline__ void ldsm_x4(uint32_t& r0, uint32_t& r1, uint32_t& r2, uint32_t& r3,
                                        uint32_t addr) {
    asm volatile("ldmatrix.sync.aligned.m8n8.x4.shared.b16 {%0,%1,%2,%3}, [%4];"
                 : "=r"(r0), "=r"(r1), "=r"(r2), "=r"(r3) : "r"(addr));
}
__device__ __forceinline__ void hmma16816(float* c, uint32_t a0, uint32_t a1, uint32_t a2,
                                          uint32_t a3, uint32_t b0, uint32_t b1) {
    asm volatile(
        "mma.sync.aligned.m16n8k16.row.col.f32.bf16.bf16.f32 "
        "{%0,%1,%2,%3}, {%4,%5,%6,%7}, {%8,%9}, {%0,%1,%2,%3};"
        : "+f"(c[0]), "+f"(c[1]), "+f"(c[2]), "+f"(c[3])
        : "r"(a0), "r"(a1), "r"(a2), "r"(a3), "r"(b0), "r"(b1));
}
__device__ __forceinline__ unsigned long long fma2(unsigned long long a, unsigned long long b,
                                                   unsigned long long c) {
    unsigned long long d;
    asm("fma.rn.f32x2 %0, %1, %2, %3;" : "=l"(d) : "l"(a), "l"(b), "l"(c));
    return d;
}
__device__ __forceinline__ float2 unpack2(unsigned long long v) {
    float2 r;
    asm("mov.b64 {%0, %1}, %2;" : "=f"(r.x), "=f"(r.y) : "l"(v));
    return r;
}
__device__ __forceinline__ uint32_t pack_bf16(float a, float b) {
    __nv_bfloat16 ah = __float2bfloat16_rn(a), bh = __float2bfloat16_rn(b);
    return (uint32_t)__bfloat16_as_ushort(ah) | ((uint32_t)__bfloat16_as_ushort(bh) << 16);
}
__device__ __forceinline__ uint32_t pack_bf16_lo(float a, float b) {
    __nv_bfloat16 ah = __float2bfloat16_rn(a), bh = __float2bfloat16_rn(b);
    float al = a - __bfloat162float(ah), bl = b - __bfloat162float(bh);
    return (uint32_t)__bfloat16_as_ushort(__float2bfloat16_rn(al)) |
           ((uint32_t)__bfloat16_as_ushort(__float2bfloat16_rn(bl)) << 16);
}

// ---------------- kernel 0: e norms, e split [hi|lo|hi], zero flags ----------------
__global__ void vq_init(const float* __restrict__ embed) {
    int c = blockIdx.x * 256 + threadIdx.x;
    if (c == 0) g_hardcnt = 0;
    if (c < NC) {
        const float* e = embed + (size_t)c * DD;
        float s = 0.f;
        #pragma unroll 8
        for (int k = 0; k < DD; ++k) s = __fmaf_rn(e[k], e[k], s);
        g_enorm[c] = s;
        g_used[c] = 0.f;
        uint32_t* dst = reinterpret_cast<uint32_t*>(g_esplit + (size_t)c * KDIM);
        #pragma unroll 4
        for (int w = 0; w < 64; ++w) {
            float a = e[2 * w], b = e[2 * w + 1];
            dst[w]       = pack_bf16(a, b);
            dst[64 + w]  = pack_bf16_lo(a, b);
            dst[128 + w] = pack_bf16(a, b);
        }
    }
}

// ---------------- kernel 1: x transpose + split [hi|hi|lo] + row norms ----------------
#define CS 129
__global__ void __launch_bounds__(256) vq_convert(const float* __restrict__ x) {
    extern __shared__ float xs[];
    const int tid = threadIdx.x;
    const int t0 = blockIdx.x * 128;
    const int bb = blockIdx.y;
    const float* xb = x + (size_t)bb * DD * TT;

    #pragma unroll
    for (int it = 0; it < 16; ++it) {
        int f = tid + it * 256;
        int d = f >> 5;
        int v = f & 31;
        float4 val = *reinterpret_cast<const float4*>(xb + (size_t)d * TT + t0 + v * 4);
        xs[(v * 4 + 0) * CS + d] = val.x;
        xs[(v * 4 + 1) * CS + d] = val.y;
        xs[(v * 4 + 2) * CS + d] = val.z;
        xs[(v * 4 + 3) * CS + d] = val.w;
    }
    __syncthreads();

    if (tid < 128) {
        float s = 0.f;
        #pragma unroll 8
        for (int k = 0; k < DD; ++k) { float v = xs[tid * CS + k]; s = __fmaf_rn(v, v, s); }
        g_rq[(size_t)bb * TT + t0 + tid] = s;
    }

    {
        const int row  = tid >> 1;
        const int half = tid & 1;
        const float* xr = xs + row * CS;
        uint32_t* out = reinterpret_cast<uint32_t*>(g_xsplit) +
                        ((size_t)bb * TT + t0 + row) * (KDIM / 2) + half * 96;
        #pragma unroll 4
        for (int i = 0; i < 96; ++i) {
            int w = half * 96 + i;
            uint32_t v;
            if (w < 64)        v = pack_bf16(xr[2 * w], xr[2 * w + 1]);
            else if (w < 128)  v = pack_bf16(xr[2 * (w - 64)], xr[2 * (w - 64) + 1]);
            else               v = pack_bf16_lo(xr[2 * (w - 128)], xr[2 * (w - 128) + 1]);
            out[i] = v;
        }
    }
}

// ---------------- kernel 2: HMMA GEMM + best/second argmin (ldmatrix fragments) ----------------
#define ASM_BYTES (128 * KPAD * 2)
#define BBUF_BYTES (64 * KPAD * 2)
#define SMEM_MMA (ASM_BYTES + 2 * BBUF_BYTES)

__global__ void __launch_bounds__(256) vq_mma(void) {
    extern __shared__ char smem[];
    const uint32_t As_a = smem_u32(smem);
    const uint32_t Bs_a = As_a + ASM_BYTES;

    const int tid = threadIdx.x;
    const int wid = tid >> 5, lane = tid & 31;
    const int g = lane >> 2, t4 = lane & 3;
    const int m0 = wid * 16;
    const int row0 = blockIdx.x * 128;

    const char* xsrc = reinterpret_cast<const char*>(g_xsplit) + (size_t)row0 * ROWB;
    const char* esrc = reinterpret_cast<const char*>(g_esplit);

    // Prologue: group0 = {A, B0}; group1 = {B1}
    #pragma unroll
    for (int i = 0; i < 24; ++i) {
        int f = tid + i * 256;
        int r = f / 48, v = f % 48;
        cp_async16(As_a + r * (KPAD * 2) + v * 16, xsrc + (size_t)r * ROWB + v * 16);
    }
    #pragma unroll
    for (int i = 0; i < 12; ++i) {
        int f = tid + i * 256;
        int cc = f / 48, v = f % 48;
        cp_async16(Bs_a + cc * (KPAD * 2) + v * 16, esrc + (size_t)cc * ROWB + v * 16);
    }
    cp_commit();
    #pragma unroll
    for (int i = 0; i < 12; ++i) {
        int f = tid + i * 256;
        int cc = f / 48, v = f % 48;
        cp_async16(Bs_a + BBUF_BYTES + cc * (KPAD * 2) + v * 16,
                   esrc + (size_t)(64 + cc) * ROWB + v * 16);
    }
    cp_commit();

    const float rq0 = g_rq[row0 + m0 + g];
    const float rq1 = g_rq[row0 + m0 + g + 8];
    float best0 = 3.4e38f, sec0 = 3.4e38f; int idx0 = 0;
    float best1 = 3.4e38f, sec1 = 3.4e38f; int idx1 = 0;

    // ldmatrix lane base addresses (+= ks*32 per k-step); stride 784 ≡ 16 mod 128
    const uint32_t a_addr0 = As_a + (uint32_t)(m0 + (lane & 7) + ((lane >> 3) & 1) * 8) * (KPAD * 2)
                                  + (uint32_t)(lane >> 4) * 16;
    const uint32_t b_row   = (uint32_t)((lane & 7) + (lane >> 4) * 8);
    const uint32_t b_koff  = (uint32_t)((lane >> 3) & 1) * 16;

    for (int ct = 0; ct < 16; ++ct) {
        if (ct < 15) cp_wait1(); else cp_wait0();
        __syncthreads();   // B_ct resident in buffer (ct&1)

        const uint32_t Bc_a = Bs_a + (uint32_t)(ct & 1) * BBUF_BYTES;
        float acc[8][4];
        #pragma unroll
        for (int nt = 0; nt < 8; ++nt)
            #pragma unroll
            for (int r = 0; r < 4; ++r) acc[nt][r] = 0.f;

        #pragma unroll 4
        for (int ks = 0; ks < KDIM / 16; ++ks) {
            uint32_t a0, a1, a2, a3;
            ldsm_x4(a0, a1, a2, a3, a_addr0 + (uint32_t)ks * 32);
            #pragma unroll
            for (int p = 0; p < 4; ++p) {
                uint32_t b0, b1, b2, b3;
                uint32_t baddr = Bc_a + (uint32_t)(p * 16 + b_row) * (KPAD * 2) + b_koff
                                      + (uint32_t)ks * 32;
                ldsm_x4(b0, b1, b2, b3, baddr);
                hmma16816(acc[2 * p],     a0, a1, a2, a3, b0, b1);
                hmma16816(acc[2 * p + 1], a0, a1, a2, a3, b2, b3);
            }
        }

        // distances + best/second (ascending cols -> lowest-index ties)
        #pragma unroll
        for (int nt = 0; nt < 8; ++nt) {
            int col = ct * 64 + nt * 8 + t4 * 2;
            float en0 = __ldg(&g_enorm[col]);
            float en1 = __ldg(&g_enorm[col + 1]);
            float s00 = __fadd_rn(__fsub_rn(rq0, __fmul_rn(2.f, acc[nt][0])), en0);
            float s01 = __fadd_rn(__fsub_rn(rq0, __fmul_rn(2.f, acc[nt][1])), en1);
            float s10 = __fadd_rn(__fsub_rn(rq1, __fmul_rn(2.f, acc[nt][2])), en0);
            float s11 = __fadd_rn(__fsub_rn(rq1, __fmul_rn(2.f, acc[nt][3])), en1);
            if (s00 < best0) { sec0 = best0; best0 = s00; idx0 = col; }
            else if (s00 < sec0) sec0 = s00;
            if (s01 < best0) { sec0 = best0; best0 = s01; idx0 = col + 1; }
            else if (s01 < sec0) sec0 = s01;
            if (s10 < best1) { sec1 = best1; best1 = s10; idx1 = col; }
            else if (s10 < sec1) sec1 = s10;
            if (s11 < best1) { sec1 = best1; best1 = s11; idx1 = col + 1; }
            else if (s11 < sec1) sec1 = s11;
        }
        __syncthreads();   // all warps past LDSM before overwriting buffer (ct&1)
        if (ct + 2 < 16) {
            uint32_t dstb = Bs_a + (uint32_t)(ct & 1) * BBUF_BYTES;
            const char* src = esrc + (size_t)(ct + 2) * 64 * ROWB;
            #pragma unroll
            for (int i = 0; i < 12; ++i) {
                int f = tid + i * 256;
                int cc = f / 48, v = f % 48;
                cp_async16(dstb + cc * (KPAD * 2) + v * 16, src + (size_t)cc * ROWB + v * 16);
            }
            cp_commit();
        }
    }

    #pragma unroll
    for (int off = 1; off <= 2; off <<= 1) {
        float ob0 = __shfl_xor_sync(0xffffffffu, best0, off);
        float os0 = __shfl_xor_sync(0xffffffffu, sec0, off);
        int   oi0 = __shfl_xor_sync(0xffffffffu, idx0, off);
        float ns0 = fminf(fminf(sec0, os0), fmaxf(best0, ob0));
        if (ob0 < best0 || (ob0 == best0 && oi0 < idx0)) { best0 = ob0; idx0 = oi0; }
        sec0 = ns0;
        float ob1 = __shfl_xor_sync(0xffffffffu, best1, off);
        float os1 = __shfl_xor_sync(0xffffffffu, sec1, off);
        int   oi1 = __shfl_xor_sync(0xffffffffu, idx1, off);
        float ns1 = fminf(fminf(sec1, os1), fmaxf(best1, ob1));
        if (ob1 < best1 || (ob1 == best1 && oi1 < idx1)) { best1 = ob1; idx1 = oi1; }
        sec1 = ns1;
    }

    if (t4 == 0) {
        int r0 = row0 + m0 + g;
        int r1 = r0 + 8;
        g_rowd2[r0] = best0; g_indices[r0] = idx0;
        g_rowd2[r1] = best1; g_indices[r1] = idx1;
        if (sec0 - best0 <= MARGIN) { int h = atomicAdd(&g_hardcnt, 1); g_hard[h] = r0; }
        else g_used[idx0] = 1.f;
        if (sec1 - best1 <= MARGIN) { int h = atomicAdd(&g_hardcnt, 1); g_hard[h] = r1; }
        else g_used[idx1] = 1.f;
    }
}

// ---------------- kernel 3: exact rescore as tiled GEMM (R3-proven chain) ----------------
// grid (8 code-splits, 32 tile-slots); CTA = 64 gathered rows x 128 codes.
#define SPAD 132
#define RS_SMEM ((64 * SPAD + 64 * 128 + 64) * 4)

__global__ void __launch_bounds__(256) vq_rescore(const float* __restrict__ x,
                                                  const float* __restrict__ embed) {
    extern __shared__ float sm[];
    float* xs    = sm;                   // [64][SPAD]
    float* es    = xs + 64 * SPAD;       // [64][128] swizzled
    float* rowsq = es + 64 * 128;        // [64]
    __shared__ int rows[64];

    const int tid = threadIdx.x;
    const int tx = tid & 15, ty = tid >> 4;
    const int split = blockIdx.x;        // 0..7 -> codes [split*128, +128)
    const int cnt = g_hardcnt;

    for (int tile = blockIdx.y; tile * 64 < cnt; tile += gridDim.y) {
        const int nrows = min(64, cnt - tile * 64);
        if (tid < 64) rows[tid] = g_hard[tile * 64 + min(tid, nrows - 1)];
        __syncthreads();

        #pragma unroll 4
        for (int f = tid; f < 64 * 128; f += 256) {
            int r = f >> 7, d = f & 127;
            int row = rows[r];
            int bb = row >> 12, t = row & 4095;
            xs[r * SPAD + d] = __ldg(&x[((size_t)bb * DD + d) * TT + t]);
        }
        __syncthreads();
        if (tid < 64) {
            float s = 0.f;
            #pragma unroll 8
            for (int k = 0; k < DD; ++k) { float v = xs[tid * SPAD + k]; s = __fmaf_rn(v, v, s); }
            rowsq[tid] = s;
        }

        float best[4];
        int   bidx[4];
        #pragma unroll
        for (int i = 0; i < 4; ++i) { best[i] = 3.4e38f; bidx[i] = 0; }
        const int r0 = ty * 4;
        const int cb = tx * 4;
        const int sx = tx & 7;
        float rq[4];
        bool rq_ld = false;

        for (int ct = 0; ct < 2; ++ct) {
            const int c0 = split * 128 + ct * 64;
            __syncthreads();
            if (!rq_ld) {
                #pragma unroll
                for (int i = 0; i < 4; ++i) rq[i] = rowsq[r0 + i];
                rq_ld = true;
            }
            #pragma unroll
            for (int it = 0; it < 8; ++it) {
                int f  = tid + it * 256;
                int cc = f >> 5;
                int v  = f & 31;
                float4 val = *reinterpret_cast<const float4*>(embed + (size_t)(c0 + cc) * DD + v * 4);
                int vs = v ^ ((cc >> 2) & 7);
                *reinterpret_cast<float4*>(es + cc * 128 + vs * 4) = val;
            }
            __syncthreads();

            unsigned long long acc[4][4];
            #pragma unroll
            for (int i = 0; i < 4; ++i)
                #pragma unroll
                for (int j = 0; j < 4; ++j) acc[i][j] = 0ull;

            #pragma unroll 4
            for (int kc = 0; kc < 32; ++kc) {
                const int k  = kc * 4;
                const int ko = (kc ^ sx) * 4;
                ulonglong2 xu[4], eu[4];
                #pragma unroll
                for (int i = 0; i < 4; ++i)
                    xu[i] = *reinterpret_cast<const ulonglong2*>(xs + (r0 + i) * SPAD + k);
                #pragma unroll
                for (int j = 0; j < 4; ++j)
                    eu[j] = *reinterpret_cast<const ulonglong2*>(es + (cb + j) * 128 + ko);
                #pragma unroll
                for (int i = 0; i < 4; ++i)
                    #pragma unroll
                    for (int j = 0; j < 4; ++j) {
                        acc[i][j] = fma2(xu[i].x, eu[j].x, acc[i][j]);
                        acc[i][j] = fma2(xu[i].y, eu[j].y, acc[i][j]);
                    }
            }

            #pragma unroll
            for (int j = 0; j < 4; ++j) {
                int c = c0 + cb + j;
                float en = __ldg(&g_enorm[c]);
                #pragma unroll
                for (int i = 0; i < 4; ++i) {
                    float2 p = unpack2(acc[i][j]);
                    float dot = __fadd_rn(p.x, p.y);
                    float s = __fadd_rn(__fsub_rn(rq[i], __fmul_rn(2.f, dot)), en);
                    if (s < best[i]) { best[i] = s; bidx[i] = c; }
                }
            }
        }

        #pragma unroll
        for (int off = 8; off >= 1; off >>= 1) {
            #pragma unroll
            for (int i = 0; i < 4; ++i) {
                float ov = __shfl_xor_sync(0xffffffffu, best[i], off);
                int   oi = __shfl_xor_sync(0xffffffffu, bidx[i], off);
                if (ov < best[i] || (ov == best[i] && oi < bidx[i])) { best[i] = ov; bidx[i] = oi; }
            }
        }
        if (tx == 0) {
            #pragma unroll
            for (int i = 0; i < 4; ++i) {
                int slot = tile * 64 + r0 + i;
                if (slot < cnt) {
                    g_cand_val[split * NN + slot] = best[i];
                    g_cand_idx[split * NN + slot] = bidx[i];
                }
            }
        }
        __syncthreads();
    }
}

// ---------------- kernel 3b: merge split candidates ----------------
__global__ void __launch_bounds__(256) vq_merge(void) {
    const int cnt = g_hardcnt;
    for (int h = blockIdx.x * 256 + threadIdx.x; h < cnt; h += gridDim.x * 256) {
        float best = g_cand_val[h];
        int   bidx = g_cand_idx[h];
        #pragma unroll
        for (int s = 1; s < 8; ++s) {
            float v = g_cand_val[s * NN + h];
            if (v < best) { best = v; bidx = g_cand_idx[s * NN + h]; }
        }
        int row = g_hard[h];
        g_indices[row] = bidx;
        g_rowd2[row] = best;
        g_used[bidx] = 1.f;
    }
}

// ---------------- kernel 4: gather + transposed write (+ indices as f32) ----------------
#define WPAD 133
__global__ void __launch_bounds__(256) vq_write(const float* __restrict__ embed,
                                                float* __restrict__ out,
                                                int write_idx) {
    extern __shared__ float sm[];
    int*   sidx = (int*)sm;
    float* srow = sm + 128;
    const int tid = threadIdx.x;
    const int t0 = blockIdx.x * 128;
    const int bb = blockIdx.y;
    const int nbase = bb * TT + t0;

    if (tid < 128) {
        int c = g_indices[nbase + tid];
        sidx[tid] = c;
        if (write_idx) out[(size_t)QELEMS + nbase + tid] = (float)c;
    }
    __syncthreads();
    #pragma unroll 4
    for (int it = 0; it < 16; ++it) {
        int f = tid + it * 256;
        int tl = f >> 5;
        int v  = f & 31;
        float4 val = *reinterpret_cast<const float4*>(embed + (size_t)sidx[tl] * DD + v * 4);
        float* dst = srow + tl * WPAD + v * 4;
        dst[0] = val.x; dst[1] = val.y; dst[2] = val.z; dst[3] = val.w;
    }
    __syncthreads();
    float* ob = out + (size_t)bb * DD * TT + t0;
    #pragma unroll 8
    for (int it = 0; it < 64; ++it) {
        int f = tid + it * 256;
        int d = f >> 7;
        int t = f & 127;
        ob[(size_t)d * TT + t] = srow[t * WPAD + d];
    }
}

// ---------------- kernel 5: loss partials ----------------
__global__ void __launch_bounds__(256) vq_reduce(void) {
    __shared__ float s1[256];
    const int tid = threadIdx.x;
    const int base = blockIdx.x * 512;
    s1[tid] = __fadd_rn(g_rowd2[base + tid * 2], g_rowd2[base + tid * 2 + 1]);
    __syncthreads();
    for (int off = 128; off > 0; off >>= 1) {
        if (tid < off) s1[tid] += s1[tid + off];
        __syncthreads();
    }
    if (tid == 0) g_partial[blockIdx.x] = s1[0];
}

// ---------------- kernel 6: finalize ----------------
__global__ void vq_finalize(float* __restrict__ out, int out_size) {
    __shared__ float s1[256], s2[256];
    int tid = threadIdx.x;
    float a = 0.f, b = 0.f;
    if (tid < 128) a = g_partial[tid];
    for (int i = tid; i < NC; i += 256) b += g_used[i];
    s1[tid] = a; s2[tid] = b;
    __syncthreads();
    for (int off = 128; off > 0; off >>= 1) {
        if (tid < off) { s1[tid] += s1[tid + off]; s2[tid] += s2[tid + off]; }
        __syncthreads();
    }
    if (tid == 0) {
        long long base = (long long)QELEMS + NN;
        if ((long long)out_size >= base + 2) {
            out[base]     = 2.0f * s1[0] / ((float)NN * (float)DD);
            out[base + 1] = s2[0] / (float)NC;
        }
    }
}

// ---------------- launch ----------------
extern "C" void kernel_launch(void* const* d_in, const int* in_sizes, int n_in,
                              void* d_out, int out_size) {
    const float* x     = (const float*)d_in[0];
    const float* embed = (const float*)d_in[1];
    float* out = (float*)d_out;

    const int smemC = 128 * CS * (int)sizeof(float);
    const int smemW = (128 + 128 * WPAD) * (int)sizeof(float);
    cudaFuncSetAttribute(vq_convert, cudaFuncAttributeMaxDynamicSharedMemorySize, smemC);
    cudaFuncSetAttribute(vq_mma,     cudaFuncAttributeMaxDynamicSharedMemorySize, SMEM_MMA);
    cudaFuncSetAttribute(vq_rescore, cudaFuncAttributeMaxDynamicSharedMemorySize, RS_SMEM);
    cudaFuncSetAttribute(vq_write,   cudaFuncAttributeMaxDynamicSharedMemorySize, smemW);

    int write_idx = (out_size >= QELEMS + NN) ? 1 : 0;

    vq_init<<<(NC + 255) / 256, 256>>>(embed);
    dim3 gc(TT / 128, BB);
    vq_convert<<<gc, 256, smemC>>>(x);
    vq_mma<<<NN / 128, 256, SMEM_MMA>>>();
    dim3 gr(8, 32);
    vq_rescore<<<gr, 256, RS_SMEM>>>(x, embed);
    vq_merge<<<32, 256>>>();
    vq_write<<<gc, 256, smemW>>>(embed, out, write_idx);
    vq_reduce<<<NN / 512, 256>>>();
    vq_finalize<<<1, 256>>>(out, out_size);
}